// round 9
// baseline (speedup 1.0000x reference)
#include <cuda_runtime.h>

#define HH 16
#define NN 8192
#define DD 64
#define WW 128
#define NEGF (-1e30f)
#define LOG2E 1.4426950408889634f

typedef unsigned long long ull;

// ---------- packed f32x2 helpers (sm_103a; ptxas won't auto-fuse, must be PTX) ----------
__device__ __forceinline__ ull fma2(ull a, ull b, ull c) {
    ull d; asm("fma.rn.f32x2 %0,%1,%2,%3;" : "=l"(d) : "l"(a), "l"(b), "l"(c)); return d;
}
__device__ __forceinline__ ull add2(ull a, ull b) {
    ull d; asm("add.rn.f32x2 %0,%1,%2;" : "=l"(d) : "l"(a), "l"(b)); return d;
}
__device__ __forceinline__ ull mul2(ull a, ull b) {
    ull d; asm("mul.rn.f32x2 %0,%1,%2;" : "=l"(d) : "l"(a), "l"(b)); return d;
}
__device__ __forceinline__ ull pack2(float x) {
    unsigned xi = __float_as_uint(x);
    ull r; asm("mov.b64 %0,{%1,%2};" : "=l"(r) : "r"(xi), "r"(xi)); return r;
}
__device__ __forceinline__ float2 unpack2(ull v) {
    unsigned lo, hi; asm("mov.b64 {%0,%1},%2;" : "=r"(lo), "=r"(hi) : "l"(v));
    return make_float2(__uint_as_float(lo), __uint_as_float(hi));
}

// Fast 2^x for x <= 0 on the FMA/ALU/CVT pipes (no MUFU). ~1.5e-5 rel err.
// Returns 2^max(x,-126): masked lanes must be zeroed by the caller's select.
__device__ __forceinline__ float exp2n(float x) {
    x = fmaxf(x, -126.0f);
    float fi = floorf(x);
    float f = x - fi;                 // f in [0,1)
    float p = 1.5404072e-4f;          // Taylor of 2^f: ln2^k/k!
    p = fmaf(p, f, 1.3333558e-3f);
    p = fmaf(p, f, 9.6181291e-3f);
    p = fmaf(p, f, 5.5504109e-2f);
    p = fmaf(p, f, 2.4022651e-1f);
    p = fmaf(p, f, 6.9314718e-1f);
    p = fmaf(p, f, 1.0f);
    float sc = __uint_as_float((unsigned)((int)fi + 127) << 23);
    return p * sc;
}

// ---------- pooled K/V scratch (no allocation allowed -> device globals) ----------
__device__ float g_k1[HH * 1024 * DD];
__device__ float g_v1[HH * 1024 * DD];
__device__ float g_k2[HH * 128 * DD];
__device__ float g_v2[HH * 128 * DD];
__device__ float g_k3[HH * 16 * DD];
__device__ float g_v3[HH * 16 * DD];

// level-1 pooling: raw k/v (H,8192,64) -> (H,1024,64) mean over 8
__global__ void pool_l1(const float* __restrict__ k, const float* __restrict__ v) {
    int idx = blockIdx.x * 256 + threadIdx.x;     // 16*1024*64 = 1048576, exact
    int dd = idx & 63;
    int c  = (idx >> 6) & 1023;
    int h  = idx >> 16;
    const float* pk = k + ((size_t)h * NN + c * 8) * DD + dd;
    const float* pv = v + ((size_t)h * NN + c * 8) * DD + dd;
    float sk = 0.f, sv = 0.f;
#pragma unroll
    for (int r = 0; r < 8; r++) { sk += pk[r * DD]; sv += pv[r * DD]; }
    g_k1[idx] = sk * 0.125f;
    g_v1[idx] = sv * 0.125f;
}

// level-2 pooling: (H,1024,64) -> (H,128,64)
__global__ void pool_l2() {
    int idx = blockIdx.x * 256 + threadIdx.x;     // 16*128*64 = 131072, exact
    int dd = idx & 63;
    int c  = (idx >> 6) & 127;
    int h  = idx >> 13;
    const float* pk = g_k1 + ((size_t)h * 1024 + c * 8) * DD + dd;
    const float* pv = g_v1 + ((size_t)h * 1024 + c * 8) * DD + dd;
    float sk = 0.f, sv = 0.f;
#pragma unroll
    for (int r = 0; r < 8; r++) { sk += pk[r * DD]; sv += pv[r * DD]; }
    g_k2[idx] = sk * 0.125f;
    g_v2[idx] = sv * 0.125f;
}

// level-3 pooling: (H,128,64) -> (H,16,64)
__global__ void pool_l3() {
    int idx = blockIdx.x * 256 + threadIdx.x;     // 16*16*64 = 16384, exact
    int dd = idx & 63;
    int c  = (idx >> 6) & 15;
    int h  = idx >> 10;
    const float* pk = g_k2 + ((size_t)h * 128 + c * 8) * DD + dd;
    const float* pv = g_v2 + ((size_t)h * 128 + c * 8) * DD + dd;
    float sk = 0.f, sv = 0.f;
#pragma unroll
    for (int r = 0; r < 8; r++) { sk += pk[r * DD]; sv += pv[r * DD]; }
    g_k3[idx] = sk * 0.125f;
    g_v3[idx] = sv * 0.125f;
}

// ---------- main attention kernel ----------

// Load 64 rows x 64 floats of K and V into shared (zero-fill out of [0,limit))
__device__ __forceinline__ void load_tile(float* sk, float* sv,
                                          const float* __restrict__ gk,
                                          const float* __restrict__ gv,
                                          int row0, int limit) {
#pragma unroll
    for (int it = 0; it < 8; it++) {
        int idx = threadIdx.x + it * 128;         // 0..1023 over 64 rows * 16 float4
        int r   = idx >> 4;
        int c4  = idx & 15;
        int row = row0 + r;
        float4 a = make_float4(0.f, 0.f, 0.f, 0.f);
        float4 b = a;
        if (row >= 0 && row < limit) {
            a = ((const float4*)(gk + (size_t)row * DD))[c4];
            b = ((const float4*)(gv + (size_t)row * DD))[c4];
        }
        ((float4*)sk)[idx] = a;
        ((float4*)sv)[idx] = b;
    }
}

// Process up to nkeys (multiple of 16) keys resident in shared.
// All scores are in LOG2 units: q2 is pre-scaled by scale*log2e; gamma is gamma*log2e.
// LOCAL=true: key index = raw token j, valid iff 0 <= i-j < W, decay gamma*(i-j).
// LOCAL=false: key index = chunk c, j_last=(c+1)*Sz-1, valid iff i-j_last >= W.
template <bool LOCAL>
__device__ __forceinline__ void process_tile(const float* sk, const float* sv,
                                             int nkeys, int key0, int i, int Sz,
                                             float gamma,
                                             const ull* q2, ull* o2,
                                             float& m, float& l) {
#pragma unroll 1
    for (int kb = 0; kb < nkeys; kb += 16) {
        float sarr[16];
        unsigned vmask = 0;
        float cmax = NEGF;
#pragma unroll
        for (int u = 0; u < 16; u++) {
            int ci = kb + u;
            const ulonglong2* kr = (const ulonglong2*)(sk + ci * DD);
            ull a0 = 0ull, a1 = 0ull, a2 = 0ull, a3 = 0ull;
#pragma unroll
            for (int j = 0; j < 16; j += 2) {
                ulonglong2 ta = kr[j];
                ulonglong2 tb = kr[j + 1];
                a0 = fma2(q2[2 * j],     ta.x, a0);
                a1 = fma2(q2[2 * j + 1], ta.y, a1);
                a2 = fma2(q2[2 * j + 2], tb.x, a2);
                a3 = fma2(q2[2 * j + 3], tb.y, a3);
            }
            a0 = add2(a0, a1);
            a2 = add2(a2, a3);
            a0 = add2(a0, a2);
            float2 f = unpack2(a0);
            float dot = f.x + f.y;     // already includes scale*log2e

            int c = key0 + ci;
            bool valid;
            float dist;
            if (LOCAL) {
                int dj = i - c;
                valid = (dj >= 0) && (dj < WW) && (c >= 0);
                dist = (float)dj;
            } else {
                int jl = (c + 1) * Sz - 1;
                int dj = i - jl;
                valid = (dj >= WW);
                dist = (float)dj;
            }
            float s = valid ? fmaf(-gamma, dist, dot) : NEGF;
            sarr[u] = s;
            vmask |= (valid ? 1u : 0u) << u;
            cmax = fmaxf(cmax, s);
        }

        float mn  = fmaxf(m, cmax);
        float fac = exp2n(m - mn);    // m==mn==-1e30 -> exp2(0)=1, state is zero anyway
        m = mn;
        l *= fac;
        ull fac2 = pack2(fac);
#pragma unroll
        for (int j = 0; j < 32; j++) o2[j] = mul2(o2[j], fac2);

#pragma unroll
        for (int u = 0; u < 16; u++) {
            float p = ((vmask >> u) & 1u) ? exp2n(sarr[u] - m) : 0.0f;
            l += p;
            ull p2 = pack2(p);
            const ulonglong2* vr = (const ulonglong2*)(sv + (kb + u) * DD);
#pragma unroll
            for (int j = 0; j < 16; j++) {
                ulonglong2 t = vr[j];
                o2[2 * j]     = fma2(p2, t.x, o2[2 * j]);
                o2[2 * j + 1] = fma2(p2, t.y, o2[2 * j + 1]);
            }
        }
    }
}

__device__ __forceinline__ void process_level(float* sk, float* sv,
                                              const float* __restrict__ kl,
                                              const float* __restrict__ vl,
                                              int C, int Sz, float gamma,
                                              int t0, int i,
                                              const ull* q2, ull* o2,
                                              float& m, float& l) {
    int c_hi = t0 / Sz;          // max visible chunks for any query in this block
    if (c_hi > C) c_hi = C;
#pragma unroll 1
    for (int cb = 0; cb < c_hi; cb += 64) {
        __syncthreads();
        load_tile(sk, sv, kl, vl, cb, C);
        __syncthreads();
        int cend = c_hi - cb;
        if (cend > 64) cend = 64;
        int cr = (cend + 15) & ~15;   // per-key validity masks the round-up
        process_tile<false>(sk, sv, cr, cb, i, Sz, gamma, q2, o2, m, l);
    }
}

__global__ __launch_bounds__(128) void attn_kernel(const float* __restrict__ q,
                                                   const float* __restrict__ k,
                                                   const float* __restrict__ v,
                                                   const float* __restrict__ gammas,
                                                   float* __restrict__ out) {
    __shared__ __align__(16) float sk[64 * DD];
    __shared__ __align__(16) float sv[64 * DD];

    const int qt = (int)gridDim.x - 1 - (int)blockIdx.x;  // heavy tiles first
    const int h  = blockIdx.y;
    const int t0 = qt * 128;
    const int i  = t0 + (int)threadIdx.x;
    const int wid = (int)threadIdx.x >> 5;
    // log2-domain constants: scores kept in units of log2
    const float scale2 = 0.125f * LOG2E;   // (1/sqrt(64)) * log2e, folded into q regs
    const float g0 = gammas[0] * LOG2E, g1 = gammas[1] * LOG2E;
    const float g2 = gammas[2] * LOG2E, g3 = gammas[3] * LOG2E;

    ull q2[32];
    {
        const ulonglong2* qp = (const ulonglong2*)(q + ((size_t)h * NN + i) * DD);
        ull s2 = pack2(scale2);
#pragma unroll
        for (int j = 0; j < 16; j++) {
            ulonglong2 t = qp[j];
            q2[2 * j]     = mul2(t.x, s2);
            q2[2 * j + 1] = mul2(t.y, s2);
        }
    }

    float m = NEGF, l = 0.f;
    ull o2[32];
#pragma unroll
    for (int j = 0; j < 32; j++) o2[j] = 0ull;

    // ----- level 0: exact sliding window, keys in [t0-128, t0+128) -----
    const float* kh = k + (size_t)h * NN * DD;
    const float* vh = v + (size_t)h * NN * DD;
#pragma unroll 1
    for (int t = 0; t < 4; t++) {
        int j0 = t0 - 128 + t * 64;
        if (j0 + 64 <= 0) continue;   // block-uniform skip
        __syncthreads();
        load_tile(sk, sv, kh, vh, j0, NN);
        __syncthreads();
        // warp-uniform band skip: oldest tile touches only tids<=62 (warps 0,1);
        // newest tile touches only tids>=64 (warps 2,3)
        bool doproc = !((t == 0 && wid >= 2) || (t == 3 && wid < 2));
        if (doproc)
            process_tile<true>(sk, sv, 64, j0, i, 1, g0, q2, o2, m, l);
    }

    // ----- hierarchy levels -----
    process_level(sk, sv, g_k1 + (size_t)h * 1024 * DD, g_v1 + (size_t)h * 1024 * DD,
                  1024, 8, g1, t0, i, q2, o2, m, l);
    process_level(sk, sv, g_k2 + (size_t)h * 128 * DD, g_v2 + (size_t)h * 128 * DD,
                  128, 64, g2, t0, i, q2, o2, m, l);
    process_level(sk, sv, g_k3 + (size_t)h * 16 * DD, g_v3 + (size_t)h * 16 * DD,
                  16, 512, g3, t0, i, q2, o2, m, l);

    // ----- epilogue: normalize and store -----
    float invl = 1.0f / fmaxf(l, 1e-8f);
    ull inv2 = pack2(invl);
    ulonglong2* op = (ulonglong2*)(out + ((size_t)h * NN + i) * DD);
#pragma unroll
    for (int j = 0; j < 16; j++) {
        ulonglong2 t;
        t.x = mul2(o2[2 * j], inv2);
        t.y = mul2(o2[2 * j + 1], inv2);
        op[j] = t;
    }
}

extern "C" void kernel_launch(void* const* d_in, const int* in_sizes, int n_in,
                              void* d_out, int out_size) {
    const float* q      = (const float*)d_in[0];
    const float* k      = (const float*)d_in[1];
    const float* v      = (const float*)d_in[2];
    const float* gammas = (const float*)d_in[3];
    float* out = (float*)d_out;

    pool_l1<<<4096, 256>>>(k, v);
    pool_l2<<<512, 256>>>();
    pool_l3<<<64, 256>>>();

    dim3 grid(64, HH);
    attn_kernel<<<grid, 128>>>(q, k, v, gammas, out);
}

// round 14
// speedup vs baseline: 1.1878x; 1.1878x over previous
#include <cuda_runtime.h>

#define HH 16
#define NN 8192
#define DD 64
#define WW 128
#define NEGF (-1e30f)

// shared K/V tile layout: 64 rows, 72-float stride; dims 0-31 at +0, dims 32-63 at +40 floats
#define RSTRIDE 72
#define HOFF 40

typedef unsigned long long ull;

// ---------- packed f32x2 helpers ----------
__device__ __forceinline__ ull fma2(ull a, ull b, ull c) {
    ull d; asm("fma.rn.f32x2 %0,%1,%2,%3;" : "=l"(d) : "l"(a), "l"(b), "l"(c)); return d;
}
__device__ __forceinline__ ull add2(ull a, ull b) {
    ull d; asm("add.rn.f32x2 %0,%1,%2;" : "=l"(d) : "l"(a), "l"(b)); return d;
}
__device__ __forceinline__ ull mul2(ull a, ull b) {
    ull d; asm("mul.rn.f32x2 %0,%1,%2;" : "=l"(d) : "l"(a), "l"(b)); return d;
}
__device__ __forceinline__ ull pack2(float x) {
    unsigned xi = __float_as_uint(x);
    ull r; asm("mov.b64 %0,{%1,%2};" : "=l"(r) : "r"(xi), "r"(xi)); return r;
}
__device__ __forceinline__ float2 unpack2(ull v) {
    unsigned lo, hi; asm("mov.b64 {%0,%1},%2;" : "=r"(lo), "=r"(hi) : "l"(v));
    return make_float2(__uint_as_float(lo), __uint_as_float(hi));
}

// ---------- pooled K/V scratch ----------
__device__ float g_k1[HH * 1024 * DD];
__device__ float g_v1[HH * 1024 * DD];
__device__ float g_k2[HH * 128 * DD];
__device__ float g_v2[HH * 128 * DD];
__device__ float g_k3[HH * 16 * DD];
__device__ float g_v3[HH * 16 * DD];

__global__ void pool_l1(const float* __restrict__ k, const float* __restrict__ v) {
    int idx = blockIdx.x * 256 + threadIdx.x;
    int dd = idx & 63;
    int c  = (idx >> 6) & 1023;
    int h  = idx >> 16;
    const float* pk = k + ((size_t)h * NN + c * 8) * DD + dd;
    const float* pv = v + ((size_t)h * NN + c * 8) * DD + dd;
    float sk = 0.f, sv = 0.f;
#pragma unroll
    for (int r = 0; r < 8; r++) { sk += pk[r * DD]; sv += pv[r * DD]; }
    g_k1[idx] = sk * 0.125f;
    g_v1[idx] = sv * 0.125f;
}

__global__ void pool_l2() {
    int idx = blockIdx.x * 256 + threadIdx.x;
    int dd = idx & 63;
    int c  = (idx >> 6) & 127;
    int h  = idx >> 13;
    const float* pk = g_k1 + ((size_t)h * 1024 + c * 8) * DD + dd;
    const float* pv = g_v1 + ((size_t)h * 1024 + c * 8) * DD + dd;
    float sk = 0.f, sv = 0.f;
#pragma unroll
    for (int r = 0; r < 8; r++) { sk += pk[r * DD]; sv += pv[r * DD]; }
    g_k2[idx] = sk * 0.125f;
    g_v2[idx] = sv * 0.125f;
}

__global__ void pool_l3() {
    int idx = blockIdx.x * 256 + threadIdx.x;
    int dd = idx & 63;
    int c  = (idx >> 6) & 15;
    int h  = idx >> 10;
    const float* pk = g_k2 + ((size_t)h * 128 + c * 8) * DD + dd;
    const float* pv = g_v2 + ((size_t)h * 128 + c * 8) * DD + dd;
    float sk = 0.f, sv = 0.f;
#pragma unroll
    for (int r = 0; r < 8; r++) { sk += pk[r * DD]; sv += pv[r * DD]; }
    g_k3[idx] = sk * 0.125f;
    g_v3[idx] = sv * 0.125f;
}

// ---------- main attention kernel (split-d: 2 lanes per query) ----------

// Load 64 rows x 64 floats into split-bank shared layout (zero-fill out of [0,limit))
__device__ __forceinline__ void load_tile(float* sk, float* sv,
                                          const float* __restrict__ gk,
                                          const float* __restrict__ gv,
                                          int row0, int limit) {
#pragma unroll
    for (int it = 0; it < 4; it++) {
        int idx = threadIdx.x + it * 256;          // 0..1023 over 64 rows * 16 float4
        int r   = idx >> 4;
        int c4  = idx & 15;
        int row = row0 + r;
        float4 a = make_float4(0.f, 0.f, 0.f, 0.f);
        float4 b = a;
        if (row >= 0 && row < limit) {
            a = ((const float4*)(gk + (size_t)row * DD))[c4];
            b = ((const float4*)(gv + (size_t)row * DD))[c4];
        }
        int phys = r * RSTRIDE + (c4 < 8 ? c4 * 4 : HOFF + (c4 - 8) * 4);
        *(float4*)(sk + phys) = a;
        *(float4*)(sv + phys) = b;
    }
}

// q2/o2 hold this lane's 32-dim half (16 f32x2). m,l duplicated across the lane pair.
template <bool LOCAL>
__device__ __forceinline__ void process_tile(const float* sk, const float* sv,
                                             int nkeys, int key0, int i, int Sz,
                                             float gamma, int hoff,
                                             const ull* q2, ull* o2,
                                             float& m, float& l) {
#pragma unroll 1
    for (int kb = 0; kb < nkeys; kb += 8) {
        float sarr[8];
        unsigned vmask = 0;
        float cmax = NEGF;
#pragma unroll
        for (int u = 0; u < 8; u++) {
            int ci = kb + u;
            const ulonglong2* kr = (const ulonglong2*)(sk + ci * RSTRIDE + hoff);
            ull a0 = 0ull, a1 = 0ull, a2 = 0ull, a3 = 0ull;
#pragma unroll
            for (int j = 0; j < 8; j += 2) {
                ulonglong2 ta = kr[j];
                ulonglong2 tb = kr[j + 1];
                a0 = fma2(q2[2 * j],     ta.x, a0);
                a1 = fma2(q2[2 * j + 1], ta.y, a1);
                a2 = fma2(q2[2 * j + 2], tb.x, a2);
                a3 = fma2(q2[2 * j + 3], tb.y, a3);
            }
            a0 = add2(a0, a1);
            a2 = add2(a2, a3);
            a0 = add2(a0, a2);
            float2 f = unpack2(a0);
            float part = f.x + f.y;
            // combine the two 32-dim halves (lane pair 2r,2r+1)
            float dot = part + __shfl_xor_sync(0xffffffffu, part, 1);

            int c = key0 + ci;
            bool valid;
            float dist;
            if (LOCAL) {
                int dj = i - c;
                valid = (dj >= 0) && (dj < WW) && (c >= 0);
                dist = (float)dj;
            } else {
                int jl = (c + 1) * Sz - 1;
                int dj = i - jl;
                valid = (dj >= WW);
                dist = (float)dj;
            }
            float s = valid ? fmaf(-gamma, dist, dot) : NEGF;
            sarr[u] = s;
            vmask |= (valid ? 1u : 0u) << u;
            cmax = fmaxf(cmax, s);
        }

        float mn  = fmaxf(m, cmax);
        float fac = __expf(m - mn);   // m==mn==-1e30 -> exp(0)=1, state is zero anyway
        m = mn;
        l *= fac;
        ull fac2 = pack2(fac);
#pragma unroll
        for (int j = 0; j < 16; j++) o2[j] = mul2(o2[j], fac2);

#pragma unroll
        for (int u = 0; u < 8; u++) {
            float p = ((vmask >> u) & 1u) ? __expf(sarr[u] - m) : 0.0f;
            l += p;
            ull p2 = pack2(p);
            const ulonglong2* vr = (const ulonglong2*)(sv + (kb + u) * RSTRIDE + hoff);
#pragma unroll
            for (int j = 0; j < 8; j++) {
                ulonglong2 t = vr[j];
                o2[2 * j]     = fma2(p2, t.x, o2[2 * j]);
                o2[2 * j + 1] = fma2(p2, t.y, o2[2 * j + 1]);
            }
        }
    }
}

__device__ __forceinline__ void process_level(float* sk, float* sv,
                                              const float* __restrict__ kl,
                                              const float* __restrict__ vl,
                                              int C, int Sz, float gamma,
                                              int t0, int i, int hoff,
                                              const ull* q2, ull* o2,
                                              float& m, float& l) {
    int c_hi = t0 / Sz;
    if (c_hi > C) c_hi = C;
#pragma unroll 1
    for (int cb = 0; cb < c_hi; cb += 64) {
        __syncthreads();
        load_tile(sk, sv, kl, vl, cb, C);
        __syncthreads();
        int cend = c_hi - cb;
        if (cend > 64) cend = 64;
        int cr = (cend + 7) & ~7;     // per-key validity masks the round-up
        process_tile<false>(sk, sv, cr, cb, i, Sz, gamma, hoff, q2, o2, m, l);
    }
}

__global__ __launch_bounds__(256, 2) void attn_kernel(const float* __restrict__ q,
                                                      const float* __restrict__ k,
                                                      const float* __restrict__ v,
                                                      const float* __restrict__ gammas,
                                                      float* __restrict__ out) {
    __shared__ __align__(16) float sk[64 * RSTRIDE];
    __shared__ __align__(16) float sv[64 * RSTRIDE];

    const int qt   = (int)gridDim.x - 1 - (int)blockIdx.x;  // heavy tiles first
    const int h    = blockIdx.y;
    const int t0   = qt * 128;
    const int qi   = (int)threadIdx.x >> 1;     // query within tile (0..127)
    const int half = (int)threadIdx.x & 1;      // which 32-dim half
    const int hoff = half * HOFF;
    const int i    = t0 + qi;
    const int wid  = (int)threadIdx.x >> 5;     // 8 warps; warp w covers queries [16w,16w+16)
    const float scale = 0.125f;                 // 1/sqrt(64)
    const float g0 = gammas[0], g1 = gammas[1], g2 = gammas[2], g3 = gammas[3];

    // this lane's 32-dim half of q, pre-scaled
    ull q2[16];
    {
        const ulonglong2* qp = (const ulonglong2*)(q + ((size_t)h * NN + i) * DD + half * 32);
        ull s2 = pack2(scale);
#pragma unroll
        for (int j = 0; j < 8; j++) {
            ulonglong2 t = qp[j];
            q2[2 * j]     = mul2(t.x, s2);
            q2[2 * j + 1] = mul2(t.y, s2);
        }
    }

    float m = NEGF, l = 0.f;
    ull o2[16];
#pragma unroll
    for (int j = 0; j < 16; j++) o2[j] = 0ull;

    // ----- level 0: exact sliding window, keys in [t0-128, t0+128) -----
    const float* kh = k + (size_t)h * NN * DD;
    const float* vh = v + (size_t)h * NN * DD;
#pragma unroll 1
    for (int t = 0; t < 4; t++) {
        int j0 = t0 - 128 + t * 64;
        if (j0 + 64 <= 0) continue;   // block-uniform skip
        __syncthreads();
        load_tile(sk, sv, kh, vh, j0, NN);
        __syncthreads();
        // warp-uniform band skip: oldest tile only touches queries <=62 (warps 0-3);
        // newest tile only queries >=64 (warps 4-7)
        bool doproc = !((t == 0 && wid >= 4) || (t == 3 && wid < 4));
        if (doproc)
            process_tile<true>(sk, sv, 64, j0, i, 1, g0, hoff, q2, o2, m, l);
    }

    // ----- hierarchy levels -----
    process_level(sk, sv, g_k1 + (size_t)h * 1024 * DD, g_v1 + (size_t)h * 1024 * DD,
                  1024, 8, g1, t0, i, hoff, q2, o2, m, l);
    process_level(sk, sv, g_k2 + (size_t)h * 128 * DD, g_v2 + (size_t)h * 128 * DD,
                  128, 64, g2, t0, i, hoff, q2, o2, m, l);
    process_level(sk, sv, g_k3 + (size_t)h * 16 * DD, g_v3 + (size_t)h * 16 * DD,
                  16, 512, g3, t0, i, hoff, q2, o2, m, l);

    // ----- epilogue: normalize and store this lane's 32 dims -----
    float invl = 1.0f / fmaxf(l, 1e-8f);
    ull inv2 = pack2(invl);
    ulonglong2* op = (ulonglong2*)(out + ((size_t)h * NN + i) * DD + half * 32);
#pragma unroll
    for (int j = 0; j < 8; j++) {
        ulonglong2 t;
        t.x = mul2(o2[2 * j], inv2);
        t.y = mul2(o2[2 * j + 1], inv2);
        op[j] = t;
    }
}

extern "C" void kernel_launch(void* const* d_in, const int* in_sizes, int n_in,
                              void* d_out, int out_size) {
    const float* q      = (const float*)d_in[0];
    const float* k      = (const float*)d_in[1];
    const float* v      = (const float*)d_in[2];
    const float* gammas = (const float*)d_in[3];
    float* out = (float*)d_out;

    pool_l1<<<4096, 256>>>(k, v);
    pool_l2<<<512, 256>>>();
    pool_l3<<<64, 256>>>();

    dim3 grid(64, HH);
    attn_kernel<<<grid, 256>>>(q, k, v, gammas, out);
}